// round 3
// baseline (speedup 1.0000x reference)
#include <cuda_runtime.h>

// Problem constants (fixed by the reference): B=32768, N=64, H=64, N_DISCRETE=16,
// HIDDEN_FLAG=True.
#define NN 64
#define HH 64
#define TB 128
#define N_DISCRETE 16

// Masked+transposed weights: g_W1mT[i][n][h] = W1[i][h][n] * M[i][n]
// 64*64*64 floats = 1 MB, static device scratch (no allocation).
__device__ float g_W1mT[NN * NN * HH];

__global__ void prep_kernel(const float* __restrict__ W1,
                            const float* __restrict__ adj) {
    int idx = blockIdx.x * blockDim.x + threadIdx.x;  // 262144 total
    if (idx >= NN * HH * NN) return;
    int i = idx >> 12;          // node
    int n = idx & 63;           // input dim (innermost of W1)
    int h = (idx >> 6) & 63;    // hidden
    float m = adj[i * NN + n];
    // HIDDEN_FLAG: last node only sees its own (last) feature
    if (i == NN - 1 && n != NN - 1) m = 0.f;
    g_W1mT[(i << 12) + (n << 6) + h] = W1[idx] * m;
}

// ---- packed f32x2 helpers (ptxas never auto-fuses these; 2x FP32 FMA rate) ----
__device__ __forceinline__ unsigned long long fma2(unsigned long long a,
                                                   unsigned long long b,
                                                   unsigned long long c) {
    unsigned long long d;
    asm("fma.rn.f32x2 %0, %1, %2, %3;" : "=l"(d) : "l"(a), "l"(b), "l"(c));
    return d;
}
__device__ __forceinline__ unsigned long long pack2(float v) {
    unsigned long long d;
    asm("mov.b64 %0, {%1, %1};" : "=l"(d) : "f"(v));
    return d;
}
__device__ __forceinline__ void unpack2(unsigned long long p, float& lo, float& hi) {
    asm("mov.b64 {%0, %1}, %2;" : "=f"(lo), "=f"(hi) : "l"(p));
}

// Block = (b-tile of 128 rows) x (node i). 256 threads.
// Thread micro-tile: 4 b-rows x 8 h-cols, accumulated as 16 packed f32x2.
__global__ __launch_bounds__(256) void cd_main_kernel(
    const float* __restrict__ x,     // [B, 64]
    const float* __restrict__ W2,    // [64, 64]
    float* __restrict__ out)         // [B, 64]
{
    __shared__ float xsT[NN][TB];    // 32 KB; x transposed [n][b]; reused as part[] later
    __shared__ float wT[NN][HH];     // 16 KB; W1mT[i] as [n][h]

    const int i   = blockIdx.y;
    const int b0  = blockIdx.x * TB;
    const int tid = threadIdx.x;

    // ---- load W1mT[i] (4096 floats, coalesced float4) ----
    {
        const float4* src = (const float4*)(g_W1mT + (i << 12));
        float4* dst = (float4*)&wT[0][0];
        #pragma unroll
        for (int e = 0; e < 4; ++e) dst[tid + e * 256] = src[tid + e * 256];
    }

    // ---- load + gate x tile, store transposed (conflict-free STS) ----
    // thread t: b = t&127, half = t>>7 covers n in [half*32, half*32+32)
    {
        int b = tid & 127;
        int half = tid >> 7;
        const float4* xrow = (const float4*)(x + (size_t)(b0 + b) * NN + half * 32);
        #pragma unroll
        for (int j = 0; j < 8; ++j) {
            float4 v = xrow[j];
            int n = half * 32 + j * 4;
            // straight-through gating: hard - sg(soft) + soft == hard numerically
            if (n + 0 < N_DISCRETE) v.x = v.x > 0.f ? 1.f : 0.f;
            if (n + 1 < N_DISCRETE) v.y = v.y > 0.f ? 1.f : 0.f;
            if (n + 2 < N_DISCRETE) v.z = v.z > 0.f ? 1.f : 0.f;
            if (n + 3 < N_DISCRETE) v.w = v.w > 0.f ? 1.f : 0.f;
            xsT[n + 0][b] = v.x;
            xsT[n + 1][b] = v.y;
            xsT[n + 2][b] = v.z;
            xsT[n + 3][b] = v.w;
        }
    }
    __syncthreads();

    const int lane = tid & 31;
    const int wp   = tid >> 5;     // 8 warps
    const int bb0  = lane * 4;     // 4 consecutive b per lane -> float4 LDS, no conflicts
    const int h0   = wp * 8;       // 8 consecutive h per warp -> broadcast LDS

    unsigned long long acc[4][4];  // acc[b][h-pair], packed f32x2 (h0+2p, h0+2p+1)
    #pragma unroll
    for (int a = 0; a < 4; ++a)
        #pragma unroll
        for (int p = 0; p < 4; ++p) acc[a][p] = 0ull;

    #pragma unroll 8
    for (int n = 0; n < NN; ++n) {
        float4 xv = *(const float4*)&xsT[n][bb0];          // conflict-free LDS.128
        ulonglong4 wv = *(const ulonglong4*)&wT[n][h0];    // 2x broadcast LDS.128, pre-paired
        unsigned long long xb;
        xb = pack2(xv.x);
        acc[0][0] = fma2(xb, wv.x, acc[0][0]);
        acc[0][1] = fma2(xb, wv.y, acc[0][1]);
        acc[0][2] = fma2(xb, wv.z, acc[0][2]);
        acc[0][3] = fma2(xb, wv.w, acc[0][3]);
        xb = pack2(xv.y);
        acc[1][0] = fma2(xb, wv.x, acc[1][0]);
        acc[1][1] = fma2(xb, wv.y, acc[1][1]);
        acc[1][2] = fma2(xb, wv.z, acc[1][2]);
        acc[1][3] = fma2(xb, wv.w, acc[1][3]);
        xb = pack2(xv.z);
        acc[2][0] = fma2(xb, wv.x, acc[2][0]);
        acc[2][1] = fma2(xb, wv.y, acc[2][1]);
        acc[2][2] = fma2(xb, wv.z, acc[2][2]);
        acc[2][3] = fma2(xb, wv.w, acc[2][3]);
        xb = pack2(xv.w);
        acc[3][0] = fma2(xb, wv.x, acc[3][0]);
        acc[3][1] = fma2(xb, wv.y, acc[3][1]);
        acc[3][2] = fma2(xb, wv.z, acc[3][2]);
        acc[3][3] = fma2(xb, wv.w, acc[3][3]);
    }
    __syncthreads();   // everyone done reading xsT; safe to reuse it as `part`

    // ---- epilogue: relu, scale by W2, per-warp partials, smem tree reduce ----
    float w2v[8];
    #pragma unroll
    for (int k = 0; k < 8; ++k) w2v[k] = __ldg(W2 + i * HH + h0 + k);

    float* part = &xsT[0][0];      // part[8][TB], overlaid on xsT
    #pragma unroll
    for (int a = 0; a < 4; ++a) {
        float s = 0.f;
        #pragma unroll
        for (int p = 0; p < 4; ++p) {
            float lo, hi;
            unpack2(acc[a][p], lo, hi);
            s += w2v[2 * p]     * fmaxf(lo, 0.f);
            s += w2v[2 * p + 1] * fmaxf(hi, 0.f);
        }
        part[wp * TB + bb0 + a] = s;
    }
    __syncthreads();

    if (tid < TB) {
        float s = 0.f;
        #pragma unroll
        for (int w = 0; w < 8; ++w) s += part[w * TB + tid];   // deterministic order
        out[(size_t)(b0 + tid) * NN + i] = s;
    }
}

extern "C" void kernel_launch(void* const* d_in, const int* in_sizes, int n_in,
                              void* d_out, int out_size) {
    // Inputs (metadata order): t, inputs, W1, W2, adjacency, discrete_mask.
    // Index from the end so a dropped scalar `t` can't shift anything.
    const float* x   = (const float*)d_in[n_in - 5];  // [B,64]
    const float* W1  = (const float*)d_in[n_in - 4];  // [64,64,64]
    const float* W2  = (const float*)d_in[n_in - 3];  // [64,64]
    const float* adj = (const float*)d_in[n_in - 2];  // [64,64]
    // d_in[n_in-1] = discrete_mask; it is arange(64) < 16 by construction, baked in.

    float* out = (float*)d_out;
    int B = in_sizes[n_in - 5] / NN;

    prep_kernel<<<(NN * HH * NN + 255) / 256, 256>>>(W1, adj);
    dim3 grid(B / TB, NN);
    cd_main_kernel<<<grid, 256>>>(x, W2, out);
}

// round 11
// speedup vs baseline: 2.9215x; 2.9215x over previous
#include <cuda_runtime.h>
#include <cuda_bf16.h>
#include <cstdint>

// Fixed shape: B=32768, N=64, H=64, N_DISCRETE=16, HIDDEN_FLAG=True.
#define NN 64
#define HH 64
#define TB 128            // batch rows per CTA
#define G_NODES 32        // nodes per CTA (grid.y = 2)
#define THREADS 128
#define N_DISCRETE 16

// Masked weights, exact bf16 hi/lo split: W = hi + lo (residual ~2^-16).
// Layout [i][h][n] (K-major rows for the MMA B operand). 512 KB each, static.
__device__ __nv_bfloat16 g_Whi[NN * HH * NN];
__device__ __nv_bfloat16 g_Wlo[NN * HH * NN];

__global__ void prep_kernel(const float* __restrict__ W1,
                            const float* __restrict__ adj) {
    int idx = blockIdx.x * 256 + threadIdx.x;      // exactly 262144
    int i = idx >> 12;
    int n = idx & 63;
    float m = adj[i * NN + n];
    if (i == NN - 1 && n != NN - 1) m = 0.f;       // HIDDEN_FLAG: last node sees only itself
    float v = W1[idx] * m;
    __nv_bfloat16 hi = __float2bfloat16(v);
    g_Whi[idx] = hi;
    g_Wlo[idx] = __float2bfloat16(v - __bfloat162float(hi));
}

// ---------------- baseline-PTX helpers (sm_80-class only; no tcgen05) ----------
__device__ __forceinline__ uint32_t smem_u32(const void* p) {
    uint32_t a;
    asm("{ .reg .u64 t; cvta.to.shared.u64 t, %1; cvt.u32.u64 %0, t; }"
        : "=r"(a) : "l"(p));
    return a;
}
// 128B swizzle. MUST be applied to the FULL relative byte offset (row*128 + col),
// never composed as SW128(base) + delta: it XORs bits[4:6] with bits[7:9].
#define SW128(o) ((o) ^ (((o) >> 3) & 0x70))

__device__ __forceinline__ void ldsm_x4(uint32_t addr, uint32_t r[4]) {
    asm volatile("ldmatrix.sync.aligned.m8n8.x4.shared.b16 {%0,%1,%2,%3}, [%4];"
                 : "=r"(r[0]), "=r"(r[1]), "=r"(r[2]), "=r"(r[3]) : "r"(addr));
}
__device__ __forceinline__ void mma16816(float c[4], const uint32_t a[4],
                                         uint32_t b0, uint32_t b1) {
    asm volatile(
        "mma.sync.aligned.m16n8k16.row.col.f32.bf16.bf16.f32 "
        "{%0,%1,%2,%3}, {%4,%5,%6,%7}, {%8,%9}, {%0,%1,%2,%3};"
        : "+f"(c[0]), "+f"(c[1]), "+f"(c[2]), "+f"(c[3])
        : "r"(a[0]), "r"(a[1]), "r"(a[2]), "r"(a[3]), "r"(b0), "r"(b1));
}
__device__ __forceinline__ void cp16(uint32_t dst, const void* src) {
    asm volatile("cp.async.cg.shared.global [%0], [%1], 16;"
                 :: "r"(dst), "l"(src) : "memory");
}
#define CP_COMMIT() asm volatile("cp.async.commit_group;" ::: "memory")
#define CP_WAIT0()  asm volatile("cp.async.wait_group 0;"  ::: "memory")

// ---------------- SMEM layout (dynamic) ----------------------------------------
// XHI/XLO: 128 rows x 128B, SW128.  WBUF: 2 x (Whi 8K + Wlo 8K).  W2: 64x64 f32.
#define SMO_XHI   0u
#define SMO_XLO   16384u
#define SMO_WBUF  32768u
#define SMO_W2S   65536u
#define SMEM_TOTAL 81920u

__device__ __forceinline__ void load_w_async(int node, char* smem, uint32_t bufo,
                                             int tid) {
    const char* shi = (const char*)(g_Whi + ((size_t)node << 12));
    const char* slo = (const char*)(g_Wlo + ((size_t)node << 12));
    uint32_t dhi = smem_u32(smem) + SMO_WBUF + bufo;
#pragma unroll
    for (int e = 0; e < 4; ++e) {
        int j = tid + e * THREADS;                 // 0..511 (16B chunks)
        uint32_t off = SW128((uint32_t)j * 16);
        cp16(dhi + off,        shi + j * 16);
        cp16(dhi + 8192 + off, slo + j * 16);
    }
}

__global__ __launch_bounds__(THREADS) void cd_hmma_kernel(
    const float* __restrict__ x,      // [B, 64]
    const float* __restrict__ W2,     // [64, 64]
    float* __restrict__ out)          // [B, 64]
{
    extern __shared__ char smem[];
    const uint32_t sb = smem_u32(smem);
    const int tid  = threadIdx.x;
    const int wid  = tid >> 5;
    const int lane = tid & 31;
    const size_t b0 = (size_t)blockIdx.x * TB;
    const int i0 = blockIdx.y * G_NODES;

    // ---- W2 -> smem ----
    {
        const float4* w2g = (const float4*)W2;
        float4* w2s = (float4*)(smem + SMO_W2S);
#pragma unroll
        for (int e = 0; e < 8; ++e) w2s[tid + e * THREADS] = w2g[tid + e * THREADS];
    }

    // ---- first W tile prefetch (buffer 0) ----
    load_w_async(i0, smem, 0, tid);
    CP_COMMIT();

    // ---- x tile: one row/thread, gate, hi/lo split, SW128 store ----
    {
        const float4* xr = (const float4*)(x + (b0 + tid) * NN);
        float vals[NN];
#pragma unroll
        for (int q = 0; q < 16; ++q) {
            float4 v = xr[q];
            vals[4 * q] = v.x; vals[4 * q + 1] = v.y;
            vals[4 * q + 2] = v.z; vals[4 * q + 3] = v.w;
        }
#pragma unroll
        for (int n = 0; n < N_DISCRETE; ++n)       // straight-through == hard threshold
            vals[n] = vals[n] > 0.f ? 1.f : 0.f;
#pragma unroll
        for (int c = 0; c < 8; ++c) {
            __nv_bfloat16 h8[8], l8[8];
#pragma unroll
            for (int k = 0; k < 8; ++k) {
                float v = vals[c * 8 + k];
                __nv_bfloat16 h = __float2bfloat16(v);
                h8[k] = h;
                l8[k] = __float2bfloat16(v - __bfloat162float(h));
            }
            uint32_t off = SW128((uint32_t)(tid * 128 + c * 16));
            *(float4*)(smem + SMO_XHI + off) = *(const float4*)h8;
            *(float4*)(smem + SMO_XLO + off) = *(const float4*)l8;
        }
    }
    CP_WAIT0();
    __syncthreads();

    // ---- load A fragments (x) to registers ONCE; reused for all 32 nodes ----
    // Swizzle applied to the FULL relative offset (mt/k deltas inside SW128).
    uint32_t Ahi[2][4][4], Alo[2][4][4];
    {
        const uint32_t rowA = (uint32_t)(wid * 32 + (lane & 15));
        const uint32_t colA = (uint32_t)((lane >> 4) << 4);
#pragma unroll
        for (int mt = 0; mt < 2; ++mt)
#pragma unroll
            for (int k = 0; k < 4; ++k) {
                uint32_t rel = SW128(rowA * 128 + colA + (uint32_t)mt * 2048
                                     + (uint32_t)k * 32);
                ldsm_x4(sb + SMO_XHI + rel, Ahi[mt][k]);
                ldsm_x4(sb + SMO_XLO + rel, Alo[mt][k]);
            }
    }

    // ---- precompute node-invariant swizzled B offsets: [c][k][nt-pair] ----
    // lanes 0-7: h+0..7 k0-7 | 8-15: same rows k8-15 | 16-23: h+8..15 k0-7 | 24-31: k8-15
    uint32_t swB[2][4][2];
    {
        const uint32_t rowB = (uint32_t)((lane & 7) + ((lane >> 4) << 3));
        const uint32_t colB = (uint32_t)(((lane >> 3) & 1) << 4);
#pragma unroll
        for (int c = 0; c < 2; ++c)
#pragma unroll
            for (int k = 0; k < 4; ++k) {
#pragma unroll
                for (int p = 0; p < 2; ++p)
                    swB[c][k][p] = SW128(rowB * 128 + colB + (uint32_t)c * 4096
                                         + (uint32_t)p * 2048 + (uint32_t)k * 32);
            }
    }

    const float* w2s = (const float*)(smem + SMO_W2S);
    const int g2 = lane >> 2, t2 = lane & 3;

    for (int g = 0; g < G_NODES; ++g) {
        const int node = i0 + g;
        const uint32_t wb = sb + SMO_WBUF + (uint32_t)(g & 1) * 16384u;

        // prefetch next node's W under this node's MMAs
        if (g + 1 < G_NODES)
            load_w_async(node + 1, smem, (uint32_t)((g + 1) & 1) * 16384u, tid);
        CP_COMMIT();

        float s[4] = {0.f, 0.f, 0.f, 0.f};   // [mt0 g2, mt0 g2+8, mt1 g2, mt1 g2+8]

#pragma unroll
        for (int c = 0; c < 2; ++c) {        // h-chunks of 32
            float acc[2][4][4];
#pragma unroll
            for (int mt = 0; mt < 2; ++mt)
#pragma unroll
                for (int nt = 0; nt < 4; ++nt)
#pragma unroll
                    for (int e = 0; e < 4; ++e) acc[mt][nt][e] = 0.f;

#pragma unroll
            for (int k = 0; k < 4; ++k) {
                uint32_t bh0[4], bh1[4], bl0[4], bl1[4];
                ldsm_x4(wb + swB[c][k][0],        bh0);  // Whi, n-tiles 0,1
                ldsm_x4(wb + swB[c][k][1],        bh1);  // Whi, n-tiles 2,3
                ldsm_x4(wb + 8192 + swB[c][k][0], bl0);  // Wlo, n-tiles 0,1
                ldsm_x4(wb + 8192 + swB[c][k][1], bl1);  // Wlo, n-tiles 2,3
#pragma unroll
                for (int mt = 0; mt < 2; ++mt) {
                    // pass 1: x_hi * W_hi
                    mma16816(acc[mt][0], Ahi[mt][k], bh0[0], bh0[1]);
                    mma16816(acc[mt][1], Ahi[mt][k], bh0[2], bh0[3]);
                    mma16816(acc[mt][2], Ahi[mt][k], bh1[0], bh1[1]);
                    mma16816(acc[mt][3], Ahi[mt][k], bh1[2], bh1[3]);
                    // pass 2: x_lo * W_hi
                    mma16816(acc[mt][0], Alo[mt][k], bh0[0], bh0[1]);
                    mma16816(acc[mt][1], Alo[mt][k], bh0[2], bh0[3]);
                    mma16816(acc[mt][2], Alo[mt][k], bh1[0], bh1[1]);
                    mma16816(acc[mt][3], Alo[mt][k], bh1[2], bh1[3]);
                    // pass 3: x_hi * W_lo
                    mma16816(acc[mt][0], Ahi[mt][k], bl0[0], bl0[1]);
                    mma16816(acc[mt][1], Ahi[mt][k], bl0[2], bl0[3]);
                    mma16816(acc[mt][2], Ahi[mt][k], bl1[0], bl1[1]);
                    mma16816(acc[mt][3], Ahi[mt][k], bl1[2], bl1[3]);
                }
            }

            // chunk epilogue: relu + W2-weighted row sums
#pragma unroll
            for (int mt = 0; mt < 2; ++mt)
#pragma unroll
                for (int nt = 0; nt < 4; ++nt) {
                    const int h = c * 32 + nt * 8 + 2 * t2;
                    float2 w2v = *(const float2*)(w2s + node * HH + h);
                    s[mt * 2 + 0] += fmaxf(acc[mt][nt][0], 0.f) * w2v.x
                                   + fmaxf(acc[mt][nt][1], 0.f) * w2v.y;
                    s[mt * 2 + 1] += fmaxf(acc[mt][nt][2], 0.f) * w2v.x
                                   + fmaxf(acc[mt][nt][3], 0.f) * w2v.y;
                }
        }

        // reduce the 4 threads of each quad (deterministic shfl order)
#pragma unroll
        for (int j = 0; j < 4; ++j) {
            s[j] += __shfl_xor_sync(0xffffffffu, s[j], 1);
            s[j] += __shfl_xor_sync(0xffffffffu, s[j], 2);
        }
        if (t2 == 0) {
            const size_t r = b0 + wid * 32 + g2;
            out[(r)      * NN + node] = s[0];
            out[(r + 8)  * NN + node] = s[1];
            out[(r + 16) * NN + node] = s[2];
            out[(r + 24) * NN + node] = s[3];
        }

        CP_WAIT0();
        __syncthreads();   // next buffer visible to all warps
    }
}

extern "C" void kernel_launch(void* const* d_in, const int* in_sizes, int n_in,
                              void* d_out, int out_size) {
    // metadata order: t, inputs, W1, W2, adjacency, discrete_mask (index from end)
    const float* x   = (const float*)d_in[n_in - 5];
    const float* W1  = (const float*)d_in[n_in - 4];
    const float* W2  = (const float*)d_in[n_in - 3];
    const float* adj = (const float*)d_in[n_in - 2];
    float* out = (float*)d_out;
    int B = in_sizes[n_in - 5] / NN;

    static bool attr_set = false;
    if (!attr_set) {
        cudaFuncSetAttribute(cd_hmma_kernel,
                             cudaFuncAttributeMaxDynamicSharedMemorySize, SMEM_TOTAL);
        attr_set = true;
    }

    prep_kernel<<<(NN * HH * NN) / 256, 256>>>(W1, adj);
    dim3 grid(B / TB, NN / G_NODES);
    cd_hmma_kernel<<<grid, THREADS, SMEM_TOTAL>>>(x, W2, out);
}

// round 16
// speedup vs baseline: 3.2031x; 1.0964x over previous
#include <cuda_runtime.h>
#include <cuda_bf16.h>
#include <cstdint>

// Fixed shape: B=32768, N=64, H=64, N_DISCRETE=16, HIDDEN_FLAG=True.
#define NN 64
#define HH 64
#define TB 128            // batch rows per CTA
#define G_NODES 8         // nodes per CTA (grid.y = 8)
#define THREADS 128
#define N_DISCRETE 16

// Masked weights, exact bf16 hi/lo split: W = hi + lo (residual ~2^-16).
// Layout [i][h][n] (K-major rows for the MMA B operand). 512 KB each, static.
__device__ __nv_bfloat16 g_Whi[NN * HH * NN];
__device__ __nv_bfloat16 g_Wlo[NN * HH * NN];

__global__ void prep_kernel(const float* __restrict__ W1,
                            const float* __restrict__ adj) {
    int idx = blockIdx.x * 256 + threadIdx.x;      // exactly 262144
    int i = idx >> 12;
    int n = idx & 63;
    float m = adj[i * NN + n];
    if (i == NN - 1 && n != NN - 1) m = 0.f;       // HIDDEN_FLAG: last node sees only itself
    float v = W1[idx] * m;
    __nv_bfloat16 hi = __float2bfloat16(v);
    g_Whi[idx] = hi;
    g_Wlo[idx] = __float2bfloat16(v - __bfloat162float(hi));
}

// ---------------- baseline-PTX helpers (sm_80-class only; no tcgen05) ----------
__device__ __forceinline__ uint32_t smem_u32(const void* p) {
    uint32_t a;
    asm("{ .reg .u64 t; cvta.to.shared.u64 t, %1; cvt.u32.u64 %0, t; }"
        : "=r"(a) : "l"(p));
    return a;
}
// 128B swizzle. MUST be applied to the FULL relative byte offset (row*128 + col),
// never composed as SW128(base) + delta: it XORs bits[4:6] with bits[7:9].
#define SW128(o) ((o) ^ (((o) >> 3) & 0x70))

__device__ __forceinline__ void ldsm_x4(uint32_t addr, uint32_t r[4]) {
    asm volatile("ldmatrix.sync.aligned.m8n8.x4.shared.b16 {%0,%1,%2,%3}, [%4];"
                 : "=r"(r[0]), "=r"(r[1]), "=r"(r[2]), "=r"(r[3]) : "r"(addr));
}
__device__ __forceinline__ void mma16816(float c[4], const uint32_t a[4],
                                         uint32_t b0, uint32_t b1) {
    asm volatile(
        "mma.sync.aligned.m16n8k16.row.col.f32.bf16.bf16.f32 "
        "{%0,%1,%2,%3}, {%4,%5,%6,%7}, {%8,%9}, {%0,%1,%2,%3};"
        : "+f"(c[0]), "+f"(c[1]), "+f"(c[2]), "+f"(c[3])
        : "r"(a[0]), "r"(a[1]), "r"(a[2]), "r"(a[3]), "r"(b0), "r"(b1));
}
__device__ __forceinline__ void cp16(uint32_t dst, const void* src) {
    asm volatile("cp.async.cg.shared.global [%0], [%1], 16;"
                 :: "r"(dst), "l"(src) : "memory");
}
#define CP_COMMIT() asm volatile("cp.async.commit_group;" ::: "memory")
#define CP_WAIT0()  asm volatile("cp.async.wait_group 0;"  ::: "memory")

// ---------------- SMEM layout (dynamic, exactly 64 KB -> 3 CTAs/SM) -------------
// XHI/XLO: 128 rows x 128B, SW128.  WBUF: 2 x (Whi 8K + Wlo 8K).
#define SMO_XHI   0u
#define SMO_XLO   16384u
#define SMO_WBUF  32768u
#define SMEM_TOTAL 65536u

__device__ __forceinline__ void load_w_async(int node, char* smem, uint32_t bufo,
                                             int tid) {
    const char* shi = (const char*)(g_Whi + ((size_t)node << 12));
    const char* slo = (const char*)(g_Wlo + ((size_t)node << 12));
    uint32_t dhi = smem_u32(smem) + SMO_WBUF + bufo;
#pragma unroll
    for (int e = 0; e < 4; ++e) {
        int j = tid + e * THREADS;                 // 0..511 (16B chunks)
        uint32_t off = SW128((uint32_t)j * 16);
        cp16(dhi + off,        shi + j * 16);
        cp16(dhi + 8192 + off, slo + j * 16);
    }
}

__global__ __launch_bounds__(THREADS, 3) void cd_hmma_kernel(
    const float* __restrict__ x,      // [B, 64]
    const float* __restrict__ W2,     // [64, 64]
    float* __restrict__ out)          // [B, 64]
{
    extern __shared__ char smem[];
    const uint32_t sb = smem_u32(smem);
    const int tid  = threadIdx.x;
    const int wid  = tid >> 5;
    const int lane = tid & 31;
    const size_t b0 = (size_t)blockIdx.x * TB;
    const int i0 = blockIdx.y * G_NODES;

    // ---- first W tile prefetch (buffer 0) ----
    load_w_async(i0, smem, 0, tid);
    CP_COMMIT();

    // ---- x tile: one row/thread, gate, hi/lo split, SW128 store ----
    {
        const float4* xr = (const float4*)(x + (b0 + tid) * NN);
        float vals[NN];
#pragma unroll
        for (int q = 0; q < 16; ++q) {
            float4 v = xr[q];
            vals[4 * q] = v.x; vals[4 * q + 1] = v.y;
            vals[4 * q + 2] = v.z; vals[4 * q + 3] = v.w;
        }
#pragma unroll
        for (int n = 0; n < N_DISCRETE; ++n)       // straight-through == hard threshold
            vals[n] = vals[n] > 0.f ? 1.f : 0.f;
#pragma unroll
        for (int c = 0; c < 8; ++c) {
            __nv_bfloat16 h8[8], l8[8];
#pragma unroll
            for (int k = 0; k < 8; ++k) {
                float v = vals[c * 8 + k];
                __nv_bfloat16 h = __float2bfloat16(v);
                h8[k] = h;
                l8[k] = __float2bfloat16(v - __bfloat162float(h));
            }
            uint32_t off = SW128((uint32_t)(tid * 128 + c * 16));
            *(float4*)(smem + SMO_XHI + off) = *(const float4*)h8;
            *(float4*)(smem + SMO_XLO + off) = *(const float4*)l8;
        }
    }
    CP_WAIT0();
    __syncthreads();

    // ---- load A fragments (x) to registers ONCE; reused for all nodes ----
    // Swizzle applied to the FULL relative offset (mt/k deltas inside SW128).
    uint32_t Ahi[2][4][4], Alo[2][4][4];
    {
        const uint32_t rowA = (uint32_t)(wid * 32 + (lane & 15));
        const uint32_t colA = (uint32_t)((lane >> 4) << 4);
#pragma unroll
        for (int mt = 0; mt < 2; ++mt)
#pragma unroll
            for (int k = 0; k < 4; ++k) {
                uint32_t rel = SW128(rowA * 128 + colA + (uint32_t)mt * 2048
                                     + (uint32_t)k * 32);
                ldsm_x4(sb + SMO_XHI + rel, Ahi[mt][k]);
                ldsm_x4(sb + SMO_XLO + rel, Alo[mt][k]);
            }
    }

    // ---- precompute node-invariant swizzled B offsets: [c][k][nt-pair] ----
    // lanes 0-7: h+0..7 k0-7 | 8-15: same rows k8-15 | 16-23: h+8..15 k0-7 | 24-31: k8-15
    uint32_t swB[2][4][2];
    {
        const uint32_t rowB = (uint32_t)((lane & 7) + ((lane >> 4) << 3));
        const uint32_t colB = (uint32_t)(((lane >> 3) & 1) << 4);
#pragma unroll
        for (int c = 0; c < 2; ++c)
#pragma unroll
            for (int k = 0; k < 4; ++k)
#pragma unroll
                for (int p = 0; p < 2; ++p)
                    swB[c][k][p] = SW128(rowB * 128 + colB + (uint32_t)c * 4096
                                         + (uint32_t)p * 2048 + (uint32_t)k * 32);
    }

    const int g2 = lane >> 2, t2 = lane & 3;

    for (int g = 0; g < G_NODES; ++g) {
        const int node = i0 + g;
        const uint32_t wb = sb + SMO_WBUF + (uint32_t)(g & 1) * 16384u;

        // prefetch next node's W under this node's MMAs
        if (g + 1 < G_NODES) {
            load_w_async(node + 1, smem, (uint32_t)((g + 1) & 1) * 16384u, tid);
            CP_COMMIT();
        }

        float s[4] = {0.f, 0.f, 0.f, 0.f};   // [mt0 g2, mt0 g2+8, mt1 g2, mt1 g2+8]

#pragma unroll
        for (int c = 0; c < 2; ++c) {        // h-chunks of 32
            float acc[2][4][4];
#pragma unroll
            for (int mt = 0; mt < 2; ++mt)
#pragma unroll
                for (int nt = 0; nt < 4; ++nt)
#pragma unroll
                    for (int e = 0; e < 4; ++e) acc[mt][nt][e] = 0.f;

#pragma unroll
            for (int k = 0; k < 4; ++k) {
                uint32_t bh0[4], bh1[4], bl0[4], bl1[4];
                ldsm_x4(wb + swB[c][k][0],        bh0);  // Whi, n-tiles 0,1
                ldsm_x4(wb + swB[c][k][1],        bh1);  // Whi, n-tiles 2,3
                ldsm_x4(wb + 8192 + swB[c][k][0], bl0);  // Wlo, n-tiles 0,1
                ldsm_x4(wb + 8192 + swB[c][k][1], bl1);  // Wlo, n-tiles 2,3
#pragma unroll
                for (int mt = 0; mt < 2; ++mt) {
                    // pass 1: x_hi * W_hi
                    mma16816(acc[mt][0], Ahi[mt][k], bh0[0], bh0[1]);
                    mma16816(acc[mt][1], Ahi[mt][k], bh0[2], bh0[3]);
                    mma16816(acc[mt][2], Ahi[mt][k], bh1[0], bh1[1]);
                    mma16816(acc[mt][3], Ahi[mt][k], bh1[2], bh1[3]);
                    // pass 2: x_lo * W_hi
                    mma16816(acc[mt][0], Alo[mt][k], bh0[0], bh0[1]);
                    mma16816(acc[mt][1], Alo[mt][k], bh0[2], bh0[3]);
                    mma16816(acc[mt][2], Alo[mt][k], bh1[0], bh1[1]);
                    mma16816(acc[mt][3], Alo[mt][k], bh1[2], bh1[3]);
                    // pass 3: x_hi * W_lo
                    mma16816(acc[mt][0], Ahi[mt][k], bl0[0], bl0[1]);
                    mma16816(acc[mt][1], Ahi[mt][k], bl0[2], bl0[3]);
                    mma16816(acc[mt][2], Ahi[mt][k], bl1[0], bl1[1]);
                    mma16816(acc[mt][3], Ahi[mt][k], bl1[2], bl1[3]);
                }
            }

            // chunk epilogue: relu + W2-weighted row sums (W2 via L1-resident ldg)
#pragma unroll
            for (int mt = 0; mt < 2; ++mt)
#pragma unroll
                for (int nt = 0; nt < 4; ++nt) {
                    const int h = c * 32 + nt * 8 + 2 * t2;
                    const float2 w2v = __ldg((const float2*)(W2 + node * HH + h));
                    s[mt * 2 + 0] += fmaxf(acc[mt][nt][0], 0.f) * w2v.x
                                   + fmaxf(acc[mt][nt][1], 0.f) * w2v.y;
                    s[mt * 2 + 1] += fmaxf(acc[mt][nt][2], 0.f) * w2v.x
                                   + fmaxf(acc[mt][nt][3], 0.f) * w2v.y;
                }
        }

        // reduce the 4 threads of each quad (deterministic shfl order)
#pragma unroll
        for (int j = 0; j < 4; ++j) {
            s[j] += __shfl_xor_sync(0xffffffffu, s[j], 1);
            s[j] += __shfl_xor_sync(0xffffffffu, s[j], 2);
        }
        if (t2 == 0) {
            const size_t r = b0 + wid * 32 + g2;
            out[(r)      * NN + node] = s[0];
            out[(r + 8)  * NN + node] = s[1];
            out[(r + 16) * NN + node] = s[2];
            out[(r + 24) * NN + node] = s[3];
        }

        if (g + 1 < G_NODES) {
            CP_WAIT0();
            __syncthreads();   // next buffer visible to all warps
        }
    }
}

extern "C" void kernel_launch(void* const* d_in, const int* in_sizes, int n_in,
                              void* d_out, int out_size) {
    // metadata order: t, inputs, W1, W2, adjacency, discrete_mask (index from end)
    const float* x   = (const float*)d_in[n_in - 5];
    const float* W1  = (const float*)d_in[n_in - 4];
    const float* W2  = (const float*)d_in[n_in - 3];
    const float* adj = (const float*)d_in[n_in - 2];
    float* out = (float*)d_out;
    int B = in_sizes[n_in - 5] / NN;

    static bool attr_set = false;
    if (!attr_set) {
        cudaFuncSetAttribute(cd_hmma_kernel,
                             cudaFuncAttributeMaxDynamicSharedMemorySize, SMEM_TOTAL);
        attr_set = true;
    }

    prep_kernel<<<(NN * HH * NN) / 256, 256>>>(W1, adj);
    dim3 grid(B / TB, NN / G_NODES);
    cd_hmma_kernel<<<grid, THREADS, SMEM_TOTAL>>>(x, W2, out);
}